// round 14
// baseline (speedup 1.0000x reference)
#include <cuda_runtime.h>
#include <float.h>

#define N_NODES 50000
#define N_EDGES 800000
#define F 128          // HID*HEADS
#define HEADS 8
#define HID 16
#define NC 10
#define NEG 0.2f

// ---------------- scratch (device globals; no allocations allowed) ----------------
__device__ float g_feat[N_NODES * F];     // per-layer transformed features
__device__ float g_h[N_NODES * F];        // hidden state between layers
__device__ float g_el[N_NODES * HEADS];
__device__ float g_er[N_NODES * HEADS];
__device__ float g_feat10[N_NODES * NC];  // final layer features
__device__ int   g_cnt[N_NODES];
__device__ int   g_inc[N_NODES];
__device__ int   g_bsum[64];
__device__ int   g_rowptr[N_NODES + 1];
__device__ int   g_cursor[N_NODES];
__device__ int   g_esrc[N_EDGES];         // src ids grouped by dst (CSR)

// ---------------- CSR build ----------------
__global__ void k_zero(int* p, int n) {
    int i = blockIdx.x * blockDim.x + threadIdx.x;
    if (i < n) p[i] = 0;
}

__global__ void k_hist(const int* __restrict__ dst, int* cnt, int n) {
    int i = blockIdx.x * blockDim.x + threadIdx.x;
    if (i < n) atomicAdd(&cnt[dst[i]], 1);
}

__global__ __launch_bounds__(1024) void k_scan1(const int* __restrict__ cnt,
                                                int* inc, int* bsum, int n) {
    __shared__ int wsum[32];
    int i = blockIdx.x * 1024 + threadIdx.x;
    int lane = threadIdx.x & 31, w = threadIdx.x >> 5;
    int x = (i < n) ? cnt[i] : 0;
    #pragma unroll
    for (int o = 1; o < 32; o <<= 1) {
        int y = __shfl_up_sync(0xffffffffu, x, o);
        if (lane >= o) x += y;
    }
    if (lane == 31) wsum[w] = x;
    __syncthreads();
    if (w == 0) {
        int s = wsum[lane];
        #pragma unroll
        for (int o = 1; o < 32; o <<= 1) {
            int y = __shfl_up_sync(0xffffffffu, s, o);
            if (lane >= o) s += y;
        }
        wsum[lane] = s;
    }
    __syncthreads();
    if (w > 0) x += wsum[w - 1];
    if (i < n) inc[i] = x;
    if (threadIdx.x == 1023) bsum[blockIdx.x] = x;
}

__global__ void k_scan2(int* bsum, int nb) {
    if (threadIdx.x == 0 && blockIdx.x == 0) {
        int s = 0;
        for (int b = 0; b < nb; b++) { int t = bsum[b]; bsum[b] = s; s += t; }
    }
}

__global__ void k_finalize(const int* __restrict__ inc, const int* __restrict__ bsum,
                           const int* __restrict__ cnt, int* rowptr, int* cursor, int n) {
    int i = blockIdx.x * blockDim.x + threadIdx.x;
    if (i < n) {
        int e = inc[i] + bsum[i >> 10];
        rowptr[i + 1] = e;
        cursor[i] = e - cnt[i];
    }
    if (i == 0) rowptr[0] = 0;
}

__global__ void k_scatter(const int* __restrict__ src, const int* __restrict__ dst,
                          int* cursor, int* esrc, int n) {
    int i = blockIdx.x * blockDim.x + threadIdx.x;
    if (i < n) {
        int p = atomicAdd(&cursor[dst[i]], 1);
        esrc[p] = src[i];
    }
}

// ---------------- GEMM: C[M,128] = A[M,128] @ B[128,128] ----------------
__global__ __launch_bounds__(256) void k_gemm128(const float* __restrict__ A,
                                                 const float* __restrict__ B,
                                                 float* __restrict__ C, int M) {
    __shared__ float As[64][33];
    __shared__ float Bs[32][128];
    int tid = threadIdx.x;
    int tx = tid & 31, ty = tid >> 5;
    int brow = blockIdx.x * 64;

    float acc[8][4];
    #pragma unroll
    for (int m = 0; m < 8; m++)
        #pragma unroll
        for (int nn = 0; nn < 4; nn++) acc[m][nn] = 0.f;

    for (int k0 = 0; k0 < 128; k0 += 32) {
        #pragma unroll
        for (int it = 0; it < 8; it++) {
            int r = ty + it * 8;
            int gr = brow + r;
            As[r][tx] = (gr < M) ? A[gr * 128 + k0 + tx] : 0.f;
        }
        #pragma unroll
        for (int i = 0; i < 4; i++) {
            int e = tid + i * 256;              // float4 index 0..1023
            int r = e >> 5, c4 = e & 31;
            float4 v = reinterpret_cast<const float4*>(B + (size_t)(k0 + r) * 128)[c4];
            *reinterpret_cast<float4*>(&Bs[r][c4 * 4]) = v;
        }
        __syncthreads();
        #pragma unroll
        for (int k = 0; k < 32; k++) {
            float a[8];
            #pragma unroll
            for (int m = 0; m < 8; m++) a[m] = As[ty * 8 + m][k];
            float4 b = *reinterpret_cast<float4*>(&Bs[k][tx * 4]);
            #pragma unroll
            for (int m = 0; m < 8; m++) {
                acc[m][0] += a[m] * b.x;
                acc[m][1] += a[m] * b.y;
                acc[m][2] += a[m] * b.z;
                acc[m][3] += a[m] * b.w;
            }
        }
        __syncthreads();
    }
    #pragma unroll
    for (int m = 0; m < 8; m++) {
        int gr = brow + ty * 8 + m;
        if (gr < M) {
            float4 v = make_float4(acc[m][0], acc[m][1], acc[m][2], acc[m][3]);
            reinterpret_cast<float4*>(C + (size_t)gr * 128)[tx] = v;
        }
    }
}

// final layer GEMM: C[M,10] = A[M,128] @ W[128,10]; one warp per node
__global__ __launch_bounds__(256) void k_gemm10(const float* __restrict__ A,
                                                const float* __restrict__ W,
                                                float* __restrict__ C, int M) {
    __shared__ float sW[128 * NC];
    for (int i = threadIdx.x; i < 128 * NC; i += blockDim.x) sW[i] = W[i];
    __syncthreads();
    int warp = (blockIdx.x * blockDim.x + threadIdx.x) >> 5;
    int lane = threadIdx.x & 31;
    if (warp < M && lane < NC) {
        const float* a = A + (size_t)warp * 128;
        float acc = 0.f;
        #pragma unroll 8
        for (int k = 0; k < 128; k++) acc += a[k] * sW[k * NC + lane];
        C[warp * NC + lane] = acc;
    }
}

// ---------------- attention logits el/er ----------------
__global__ void k_elr(const float* __restrict__ feat, const float* __restrict__ al,
                      const float* __restrict__ ar, float* el, float* er) {
    int idx = blockIdx.x * blockDim.x + threadIdx.x;
    if (idx >= N_NODES * HEADS) return;
    int i = idx >> 3, h = idx & 7;
    const float* f = feat + (size_t)i * F + h * HID;
    float a = 0.f, b = 0.f;
    #pragma unroll
    for (int d = 0; d < HID; d++) {
        float v = f[d];
        a += v * al[h * HID + d];
        b += v * ar[h * HID + d];
    }
    el[idx] = a;
    er[idx] = b;
}

__global__ void k_elr10(const float* __restrict__ feat, const float* __restrict__ al,
                        const float* __restrict__ ar, float* el, float* er) {
    int i = blockIdx.x * blockDim.x + threadIdx.x;
    if (i >= N_NODES) return;
    const float* f = feat + (size_t)i * NC;
    float a = 0.f, b = 0.f;
    #pragma unroll
    for (int d = 0; d < NC; d++) { float v = f[d]; a += v * al[d]; b += v * ar[d]; }
    el[i] = a;
    er[i] = b;
}

// ---------------- edge softmax + aggregation, CSR by dst ----------------
// one block (128 threads) per dst node; thread t owns feature t, head = t>>4
__global__ __launch_bounds__(128) void k_edge(const float* __restrict__ feat,
                                              const float* __restrict__ el,
                                              const float* __restrict__ er,
                                              const int* __restrict__ rowptr,
                                              const int* __restrict__ esrc,
                                              float* __restrict__ hout, int activate) {
    int i = blockIdx.x;
    int t = threadIdx.x;
    int h = t >> 4, lane = t & 15;
    int b = rowptr[i], e = rowptr[i + 1];
    float er_h = er[i * HEADS + h];

    __shared__ float s_max[HEADS];
    __shared__ float s_den[HEADS];

    // pass A: per-head max of leaky_relu(el[src]+er[dst])
    float m = -FLT_MAX;
    for (int j = b + lane; j < e; j += 16) {
        int s = esrc[j];
        float x = el[s * HEADS + h] + er_h;
        x = x > 0.f ? x : NEG * x;
        m = fmaxf(m, x);
    }
    #pragma unroll
    for (int o = 8; o; o >>= 1) m = fmaxf(m, __shfl_xor_sync(0xffffffffu, m, o, 16));
    if (lane == 0) s_max[h] = m;
    __syncthreads();
    float emax = s_max[h];

    // pass B: softmax weights + feature aggregation in registers
    float acc = 0.f, den = 0.f;
    for (int j = b; j < e; j++) {
        int s = esrc[j];
        float x = el[s * HEADS + h] + er_h;
        x = x > 0.f ? x : NEG * x;
        float ex = __expf(x - emax);
        den += ex;
        acc += feat[(size_t)s * F + t] * ex;
    }
    if (lane == 0) s_den[h] = den;
    __syncthreads();
    float d = s_den[h];
    float o = d > 0.f ? acc / d : 0.f;
    if (activate) o = o > 0.f ? o : expm1f(o);
    hout[(size_t)i * F + t] = o;
}

// final layer: 1 head, 10 classes, one warp per node
__global__ __launch_bounds__(32) void k_edge10(const float* __restrict__ feat,
                                               const float* __restrict__ el,
                                               const float* __restrict__ er,
                                               const int* __restrict__ rowptr,
                                               const int* __restrict__ esrc,
                                               float* __restrict__ out) {
    int i = blockIdx.x;
    int lane = threadIdx.x;
    int b = rowptr[i], e = rowptr[i + 1];
    float er_i = er[i];

    float m = -FLT_MAX;
    for (int j = b + lane; j < e; j += 32) {
        float x = el[esrc[j]] + er_i;
        x = x > 0.f ? x : NEG * x;
        m = fmaxf(m, x);
    }
    #pragma unroll
    for (int o = 16; o; o >>= 1) m = fmaxf(m, __shfl_xor_sync(0xffffffffu, m, o));

    float acc = 0.f, den = 0.f;
    for (int j = b; j < e; j++) {
        int s = esrc[j];
        float x = el[s] + er_i;
        x = x > 0.f ? x : NEG * x;
        float ex = __expf(x - m);
        den += ex;
        if (lane < NC) acc += feat[(size_t)s * NC + lane] * ex;
    }
    float o = den > 0.f ? acc / den : 0.f;
    if (lane < NC) out[(size_t)i * NC + lane] = o;
}

// ---------------- launch ----------------
extern "C" void kernel_launch(void* const* d_in, const int* in_sizes, int n_in,
                              void* d_out, int out_size) {
    const float* h   = (const float*)d_in[0];
    const int*   src = (const int*)d_in[1];
    const int*   dst = (const int*)d_in[2];
    const float *W[5], *al[5], *ar[5];
    for (int i = 0; i < 5; i++) {
        W[i]  = (const float*)d_in[3 + 3 * i];
        al[i] = (const float*)d_in[4 + 3 * i];
        ar[i] = (const float*)d_in[5 + 3 * i];
    }
    float* out = (float*)d_out;

    float *feat, *hbuf, *el, *er, *feat10;
    int *cnt, *inc, *bsum, *rowptr, *cursor, *esrc;
    cudaGetSymbolAddress((void**)&feat,   g_feat);
    cudaGetSymbolAddress((void**)&hbuf,   g_h);
    cudaGetSymbolAddress((void**)&el,     g_el);
    cudaGetSymbolAddress((void**)&er,     g_er);
    cudaGetSymbolAddress((void**)&feat10, g_feat10);
    cudaGetSymbolAddress((void**)&cnt,    g_cnt);
    cudaGetSymbolAddress((void**)&inc,    g_inc);
    cudaGetSymbolAddress((void**)&bsum,   g_bsum);
    cudaGetSymbolAddress((void**)&rowptr, g_rowptr);
    cudaGetSymbolAddress((void**)&cursor, g_cursor);
    cudaGetSymbolAddress((void**)&esrc,   g_esrc);

    const int NB_SCAN = (N_NODES + 1023) / 1024;  // 49

    // CSR by dst
    k_zero<<<(N_NODES + 255) / 256, 256>>>(cnt, N_NODES);
    k_hist<<<(N_EDGES + 255) / 256, 256>>>(dst, cnt, N_EDGES);
    k_scan1<<<NB_SCAN, 1024>>>(cnt, inc, bsum, N_NODES);
    k_scan2<<<1, 32>>>(bsum, NB_SCAN);
    k_finalize<<<(N_NODES + 255) / 256, 256>>>(inc, bsum, cnt, rowptr, cursor, N_NODES);
    k_scatter<<<(N_EDGES + 255) / 256, 256>>>(src, dst, cursor, esrc, N_EDGES);

    // 4 GAT layers (128 -> 8x16, ELU)
    const float* hin = h;
    for (int l = 0; l < 4; l++) {
        k_gemm128<<<(N_NODES + 63) / 64, 256>>>(hin, W[l], feat, N_NODES);
        k_elr<<<(N_NODES * HEADS + 255) / 256, 256>>>(feat, al[l], ar[l], el, er);
        k_edge<<<N_NODES, 128>>>(feat, el, er, rowptr, esrc, hbuf, 1);
        hin = hbuf;
    }

    // final layer (128 -> 1x10, no activation; mean over 1 head = identity)
    k_gemm10<<<(N_NODES + 7) / 8, 256>>>(hbuf, W[4], feat10, N_NODES);
    k_elr10<<<(N_NODES + 255) / 256, 256>>>(feat10, al[4], ar[4], el, er);
    k_edge10<<<N_NODES, 32>>>(feat10, el, er, rowptr, esrc, out);
}

// round 15
// speedup vs baseline: 1.0025x; 1.0025x over previous
#include <cuda_runtime.h>
#include <float.h>

#define N_NODES 50000
#define N_EDGES 800000
#define F 128          // HID*HEADS
#define HEADS 8
#define HID 16
#define NC 10
#define NEG 0.2f

// ---------------- scratch (device globals; no allocations allowed) ----------------
__device__ float g_feat[N_NODES * F];     // per-layer transformed features
__device__ float g_h[N_NODES * F];        // hidden state between layers
__device__ float g_el[N_NODES * HEADS];
__device__ float g_er[N_NODES * HEADS];
__device__ float g_feat10[N_NODES * NC];  // final layer features
__device__ int   g_cnt[N_NODES];
__device__ int   g_inc[N_NODES];
__device__ int   g_bsum[64];
__device__ int   g_rowptr[N_NODES + 1];
__device__ int   g_cursor[N_NODES];
__device__ int   g_esrc[N_EDGES];         // src ids grouped by dst (CSR)

// ---------------- CSR build ----------------
__global__ void k_zero(int* p, int n) {
    int i = blockIdx.x * blockDim.x + threadIdx.x;
    if (i < n) p[i] = 0;
}

__global__ void k_hist(const int* __restrict__ dst, int* cnt, int n) {
    int i = blockIdx.x * blockDim.x + threadIdx.x;
    if (i < n) atomicAdd(&cnt[dst[i]], 1);
}

__global__ __launch_bounds__(1024) void k_scan1(const int* __restrict__ cnt,
                                                int* inc, int* bsum, int n) {
    __shared__ int wsum[32];
    int i = blockIdx.x * 1024 + threadIdx.x;
    int lane = threadIdx.x & 31, w = threadIdx.x >> 5;
    int x = (i < n) ? cnt[i] : 0;
    #pragma unroll
    for (int o = 1; o < 32; o <<= 1) {
        int y = __shfl_up_sync(0xffffffffu, x, o);
        if (lane >= o) x += y;
    }
    if (lane == 31) wsum[w] = x;
    __syncthreads();
    if (w == 0) {
        int s = wsum[lane];
        #pragma unroll
        for (int o = 1; o < 32; o <<= 1) {
            int y = __shfl_up_sync(0xffffffffu, s, o);
            if (lane >= o) s += y;
        }
        wsum[lane] = s;
    }
    __syncthreads();
    if (w > 0) x += wsum[w - 1];
    if (i < n) inc[i] = x;
    if (threadIdx.x == 1023) bsum[blockIdx.x] = x;
}

__global__ void k_scan2(int* bsum, int nb) {
    if (threadIdx.x == 0 && blockIdx.x == 0) {
        int s = 0;
        for (int b = 0; b < nb; b++) { int t = bsum[b]; bsum[b] = s; s += t; }
    }
}

__global__ void k_finalize(const int* __restrict__ inc, const int* __restrict__ bsum,
                           const int* __restrict__ cnt, int* rowptr, int* cursor, int n) {
    int i = blockIdx.x * blockDim.x + threadIdx.x;
    if (i < n) {
        int e = inc[i] + bsum[i >> 10];
        rowptr[i + 1] = e;
        cursor[i] = e - cnt[i];
    }
    if (i == 0) rowptr[0] = 0;
}

__global__ void k_scatter(const int* __restrict__ src, const int* __restrict__ dst,
                          int* cursor, int* esrc, int n) {
    int i = blockIdx.x * blockDim.x + threadIdx.x;
    if (i < n) {
        int p = atomicAdd(&cursor[dst[i]], 1);
        esrc[p] = src[i];
    }
}

// ---------------- GEMM: C[M,128] = A[M,128] @ B[128,128] ----------------
__global__ __launch_bounds__(256) void k_gemm128(const float* __restrict__ A,
                                                 const float* __restrict__ B,
                                                 float* __restrict__ C, int M) {
    __shared__ float As[64][33];
    __shared__ float Bs[32][128];
    int tid = threadIdx.x;
    int tx = tid & 31, ty = tid >> 5;
    int brow = blockIdx.x * 64;

    float acc[8][4];
    #pragma unroll
    for (int m = 0; m < 8; m++)
        #pragma unroll
        for (int nn = 0; nn < 4; nn++) acc[m][nn] = 0.f;

    for (int k0 = 0; k0 < 128; k0 += 32) {
        #pragma unroll
        for (int it = 0; it < 8; it++) {
            int r = ty + it * 8;
            int gr = brow + r;
            As[r][tx] = (gr < M) ? A[gr * 128 + k0 + tx] : 0.f;
        }
        #pragma unroll
        for (int i = 0; i < 4; i++) {
            int e = tid + i * 256;              // float4 index 0..1023
            int r = e >> 5, c4 = e & 31;
            float4 v = reinterpret_cast<const float4*>(B + (size_t)(k0 + r) * 128)[c4];
            *reinterpret_cast<float4*>(&Bs[r][c4 * 4]) = v;
        }
        __syncthreads();
        #pragma unroll
        for (int k = 0; k < 32; k++) {
            float a[8];
            #pragma unroll
            for (int m = 0; m < 8; m++) a[m] = As[ty * 8 + m][k];
            float4 b = *reinterpret_cast<float4*>(&Bs[k][tx * 4]);
            #pragma unroll
            for (int m = 0; m < 8; m++) {
                acc[m][0] += a[m] * b.x;
                acc[m][1] += a[m] * b.y;
                acc[m][2] += a[m] * b.z;
                acc[m][3] += a[m] * b.w;
            }
        }
        __syncthreads();
    }
    #pragma unroll
    for (int m = 0; m < 8; m++) {
        int gr = brow + ty * 8 + m;
        if (gr < M) {
            float4 v = make_float4(acc[m][0], acc[m][1], acc[m][2], acc[m][3]);
            reinterpret_cast<float4*>(C + (size_t)gr * 128)[tx] = v;
        }
    }
}

// final layer GEMM: C[M,10] = A[M,128] @ W[128,10]; one warp per node
__global__ __launch_bounds__(256) void k_gemm10(const float* __restrict__ A,
                                                const float* __restrict__ W,
                                                float* __restrict__ C, int M) {
    __shared__ float sW[128 * NC];
    for (int i = threadIdx.x; i < 128 * NC; i += blockDim.x) sW[i] = W[i];
    __syncthreads();
    int warp = (blockIdx.x * blockDim.x + threadIdx.x) >> 5;
    int lane = threadIdx.x & 31;
    if (warp < M && lane < NC) {
        const float* a = A + (size_t)warp * 128;
        float acc = 0.f;
        #pragma unroll 8
        for (int k = 0; k < 128; k++) acc += a[k] * sW[k * NC + lane];
        C[warp * NC + lane] = acc;
    }
}

// ---------------- attention logits el/er ----------------
__global__ void k_elr(const float* __restrict__ feat, const float* __restrict__ al,
                      const float* __restrict__ ar, float* el, float* er) {
    int idx = blockIdx.x * blockDim.x + threadIdx.x;
    if (idx >= N_NODES * HEADS) return;
    int i = idx >> 3, h = idx & 7;
    const float* f = feat + (size_t)i * F + h * HID;
    float a = 0.f, b = 0.f;
    #pragma unroll
    for (int d = 0; d < HID; d++) {
        float v = f[d];
        a += v * al[h * HID + d];
        b += v * ar[h * HID + d];
    }
    el[idx] = a;
    er[idx] = b;
}

__global__ void k_elr10(const float* __restrict__ feat, const float* __restrict__ al,
                        const float* __restrict__ ar, float* el, float* er) {
    int i = blockIdx.x * blockDim.x + threadIdx.x;
    if (i >= N_NODES) return;
    const float* f = feat + (size_t)i * NC;
    float a = 0.f, b = 0.f;
    #pragma unroll
    for (int d = 0; d < NC; d++) { float v = f[d]; a += v * al[d]; b += v * ar[d]; }
    el[i] = a;
    er[i] = b;
}

// ---------------- edge softmax + aggregation, CSR by dst ----------------
// one block (128 threads) per dst node; thread t owns feature t, head = t>>4
__global__ __launch_bounds__(128) void k_edge(const float* __restrict__ feat,
                                              const float* __restrict__ el,
                                              const float* __restrict__ er,
                                              const int* __restrict__ rowptr,
                                              const int* __restrict__ esrc,
                                              float* __restrict__ hout, int activate) {
    int i = blockIdx.x;
    int t = threadIdx.x;
    int h = t >> 4, lane = t & 15;
    int b = rowptr[i], e = rowptr[i + 1];
    float er_h = er[i * HEADS + h];

    __shared__ float s_max[HEADS];
    __shared__ float s_den[HEADS];

    // pass A: per-head max of leaky_relu(el[src]+er[dst])
    float m = -FLT_MAX;
    for (int j = b + lane; j < e; j += 16) {
        int s = esrc[j];
        float x = el[s * HEADS + h] + er_h;
        x = x > 0.f ? x : NEG * x;
        m = fmaxf(m, x);
    }
    #pragma unroll
    for (int o = 8; o; o >>= 1) m = fmaxf(m, __shfl_xor_sync(0xffffffffu, m, o, 16));
    if (lane == 0) s_max[h] = m;
    __syncthreads();
    float emax = s_max[h];

    // pass B: softmax weights + feature aggregation in registers
    float acc = 0.f, den = 0.f;
    for (int j = b; j < e; j++) {
        int s = esrc[j];
        float x = el[s * HEADS + h] + er_h;
        x = x > 0.f ? x : NEG * x;
        float ex = __expf(x - emax);
        den += ex;
        acc += feat[(size_t)s * F + t] * ex;
    }
    if (lane == 0) s_den[h] = den;
    __syncthreads();
    float d = s_den[h];
    float o = d > 0.f ? acc / d : 0.f;
    if (activate) o = o > 0.f ? o : expm1f(o);
    hout[(size_t)i * F + t] = o;
}

// final layer: 1 head, 10 classes, one warp per node
__global__ __launch_bounds__(32) void k_edge10(const float* __restrict__ feat,
                                               const float* __restrict__ el,
                                               const float* __restrict__ er,
                                               const int* __restrict__ rowptr,
                                               const int* __restrict__ esrc,
                                               float* __restrict__ out) {
    int i = blockIdx.x;
    int lane = threadIdx.x;
    int b = rowptr[i], e = rowptr[i + 1];
    float er_i = er[i];

    float m = -FLT_MAX;
    for (int j = b + lane; j < e; j += 32) {
        float x = el[esrc[j]] + er_i;
        x = x > 0.f ? x : NEG * x;
        m = fmaxf(m, x);
    }
    #pragma unroll
    for (int o = 16; o; o >>= 1) m = fmaxf(m, __shfl_xor_sync(0xffffffffu, m, o));

    float acc = 0.f, den = 0.f;
    for (int j = b; j < e; j++) {
        int s = esrc[j];
        float x = el[s] + er_i;
        x = x > 0.f ? x : NEG * x;
        float ex = __expf(x - m);
        den += ex;
        if (lane < NC) acc += feat[(size_t)s * NC + lane] * ex;
    }
    float o = den > 0.f ? acc / den : 0.f;
    if (lane < NC) out[(size_t)i * NC + lane] = o;
}

// ---------------- launch ----------------
extern "C" void kernel_launch(void* const* d_in, const int* in_sizes, int n_in,
                              void* d_out, int out_size) {
    const float* h   = (const float*)d_in[0];
    const int*   src = (const int*)d_in[1];
    const int*   dst = (const int*)d_in[2];
    const float *W[5], *al[5], *ar[5];
    for (int i = 0; i < 5; i++) {
        W[i]  = (const float*)d_in[3 + 3 * i];
        al[i] = (const float*)d_in[4 + 3 * i];
        ar[i] = (const float*)d_in[5 + 3 * i];
    }
    float* out = (float*)d_out;

    float *feat, *hbuf, *el, *er, *feat10;
    int *cnt, *inc, *bsum, *rowptr, *cursor, *esrc;
    cudaGetSymbolAddress((void**)&feat,   g_feat);
    cudaGetSymbolAddress((void**)&hbuf,   g_h);
    cudaGetSymbolAddress((void**)&el,     g_el);
    cudaGetSymbolAddress((void**)&er,     g_er);
    cudaGetSymbolAddress((void**)&feat10, g_feat10);
    cudaGetSymbolAddress((void**)&cnt,    g_cnt);
    cudaGetSymbolAddress((void**)&inc,    g_inc);
    cudaGetSymbolAddress((void**)&bsum,   g_bsum);
    cudaGetSymbolAddress((void**)&rowptr, g_rowptr);
    cudaGetSymbolAddress((void**)&cursor, g_cursor);
    cudaGetSymbolAddress((void**)&esrc,   g_esrc);

    const int NB_SCAN = (N_NODES + 1023) / 1024;  // 49

    // CSR by dst
    k_zero<<<(N_NODES + 255) / 256, 256>>>(cnt, N_NODES);
    k_hist<<<(N_EDGES + 255) / 256, 256>>>(dst, cnt, N_EDGES);
    k_scan1<<<NB_SCAN, 1024>>>(cnt, inc, bsum, N_NODES);
    k_scan2<<<1, 32>>>(bsum, NB_SCAN);
    k_finalize<<<(N_NODES + 255) / 256, 256>>>(inc, bsum, cnt, rowptr, cursor, N_NODES);
    k_scatter<<<(N_EDGES + 255) / 256, 256>>>(src, dst, cursor, esrc, N_EDGES);

    // 4 GAT layers (128 -> 8x16, ELU)
    const float* hin = h;
    for (int l = 0; l < 4; l++) {
        k_gemm128<<<(N_NODES + 63) / 64, 256>>>(hin, W[l], feat, N_NODES);
        k_elr<<<(N_NODES * HEADS + 255) / 256, 256>>>(feat, al[l], ar[l], el, er);
        k_edge<<<N_NODES, 128>>>(feat, el, er, rowptr, esrc, hbuf, 1);
        hin = hbuf;
    }

    // final layer (128 -> 1x10, no activation; mean over 1 head = identity)
    k_gemm10<<<(N_NODES + 7) / 8, 256>>>(hbuf, W[4], feat10, N_NODES);
    k_elr10<<<(N_NODES + 255) / 256, 256>>>(feat10, al[4], ar[4], el, er);
    k_edge10<<<N_NODES, 32>>>(feat10, el, er, rowptr, esrc, out);
}

// round 16
// speedup vs baseline: 1.0033x; 1.0009x over previous
#include <cuda_runtime.h>
#include <float.h>

#define N_NODES 50000
#define N_EDGES 800000
#define F 128          // HID*HEADS
#define HEADS 8
#define HID 16
#define NC 10
#define NEG 0.2f

// ---------------- scratch (device globals; no allocations allowed) ----------------
__device__ float g_feat[N_NODES * F];     // per-layer transformed features
__device__ float g_h[N_NODES * F];        // hidden state between layers
__device__ float g_el[N_NODES * HEADS];
__device__ float g_er[N_NODES * HEADS];
__device__ float g_feat10[N_NODES * NC];  // final layer features
__device__ int   g_cnt[N_NODES];
__device__ int   g_inc[N_NODES];
__device__ int   g_bsum[64];
__device__ int   g_rowptr[N_NODES + 1];
__device__ int   g_cursor[N_NODES];
__device__ int   g_esrc[N_EDGES];         // src ids grouped by dst (CSR)

// ---------------- CSR build ----------------
__global__ void k_zero(int* p, int n) {
    int i = blockIdx.x * blockDim.x + threadIdx.x;
    if (i < n) p[i] = 0;
}

__global__ void k_hist(const int* __restrict__ dst, int* cnt, int n) {
    int i = blockIdx.x * blockDim.x + threadIdx.x;
    if (i < n) atomicAdd(&cnt[dst[i]], 1);
}

__global__ __launch_bounds__(1024) void k_scan1(const int* __restrict__ cnt,
                                                int* inc, int* bsum, int n) {
    __shared__ int wsum[32];
    int i = blockIdx.x * 1024 + threadIdx.x;
    int lane = threadIdx.x & 31, w = threadIdx.x >> 5;
    int x = (i < n) ? cnt[i] : 0;
    #pragma unroll
    for (int o = 1; o < 32; o <<= 1) {
        int y = __shfl_up_sync(0xffffffffu, x, o);
        if (lane >= o) x += y;
    }
    if (lane == 31) wsum[w] = x;
    __syncthreads();
    if (w == 0) {
        int s = wsum[lane];
        #pragma unroll
        for (int o = 1; o < 32; o <<= 1) {
            int y = __shfl_up_sync(0xffffffffu, s, o);
            if (lane >= o) s += y;
        }
        wsum[lane] = s;
    }
    __syncthreads();
    if (w > 0) x += wsum[w - 1];
    if (i < n) inc[i] = x;
    if (threadIdx.x == 1023) bsum[blockIdx.x] = x;
}

__global__ void k_scan2(int* bsum, int nb) {
    if (threadIdx.x == 0 && blockIdx.x == 0) {
        int s = 0;
        for (int b = 0; b < nb; b++) { int t = bsum[b]; bsum[b] = s; s += t; }
    }
}

__global__ void k_finalize(const int* __restrict__ inc, const int* __restrict__ bsum,
                           const int* __restrict__ cnt, int* rowptr, int* cursor, int n) {
    int i = blockIdx.x * blockDim.x + threadIdx.x;
    if (i < n) {
        int e = inc[i] + bsum[i >> 10];
        rowptr[i + 1] = e;
        cursor[i] = e - cnt[i];
    }
    if (i == 0) rowptr[0] = 0;
}

__global__ void k_scatter(const int* __restrict__ src, const int* __restrict__ dst,
                          int* cursor, int* esrc, int n) {
    int i = blockIdx.x * blockDim.x + threadIdx.x;
    if (i < n) {
        int p = atomicAdd(&cursor[dst[i]], 1);
        esrc[p] = src[i];
    }
}

// ---------------- GEMM: C[M,128] = A[M,128] @ B[128,128] ----------------
__global__ __launch_bounds__(256) void k_gemm128(const float* __restrict__ A,
                                                 const float* __restrict__ B,
                                                 float* __restrict__ C, int M) {
    __shared__ float As[64][33];
    __shared__ float Bs[32][128];
    int tid = threadIdx.x;
    int tx = tid & 31, ty = tid >> 5;
    int brow = blockIdx.x * 64;

    float acc[8][4];
    #pragma unroll
    for (int m = 0; m < 8; m++)
        #pragma unroll
        for (int nn = 0; nn < 4; nn++) acc[m][nn] = 0.f;

    for (int k0 = 0; k0 < 128; k0 += 32) {
        #pragma unroll
        for (int it = 0; it < 8; it++) {
            int r = ty + it * 8;
            int gr = brow + r;
            As[r][tx] = (gr < M) ? A[gr * 128 + k0 + tx] : 0.f;
        }
        #pragma unroll
        for (int i = 0; i < 4; i++) {
            int e = tid + i * 256;              // float4 index 0..1023
            int r = e >> 5, c4 = e & 31;
            float4 v = reinterpret_cast<const float4*>(B + (size_t)(k0 + r) * 128)[c4];
            *reinterpret_cast<float4*>(&Bs[r][c4 * 4]) = v;
        }
        __syncthreads();
        #pragma unroll
        for (int k = 0; k < 32; k++) {
            float a[8];
            #pragma unroll
            for (int m = 0; m < 8; m++) a[m] = As[ty * 8 + m][k];
            float4 b = *reinterpret_cast<float4*>(&Bs[k][tx * 4]);
            #pragma unroll
            for (int m = 0; m < 8; m++) {
                acc[m][0] += a[m] * b.x;
                acc[m][1] += a[m] * b.y;
                acc[m][2] += a[m] * b.z;
                acc[m][3] += a[m] * b.w;
            }
        }
        __syncthreads();
    }
    #pragma unroll
    for (int m = 0; m < 8; m++) {
        int gr = brow + ty * 8 + m;
        if (gr < M) {
            float4 v = make_float4(acc[m][0], acc[m][1], acc[m][2], acc[m][3]);
            reinterpret_cast<float4*>(C + (size_t)gr * 128)[tx] = v;
        }
    }
}

// final layer GEMM: C[M,10] = A[M,128] @ W[128,10]; one warp per node
__global__ __launch_bounds__(256) void k_gemm10(const float* __restrict__ A,
                                                const float* __restrict__ W,
                                                float* __restrict__ C, int M) {
    __shared__ float sW[128 * NC];
    for (int i = threadIdx.x; i < 128 * NC; i += blockDim.x) sW[i] = W[i];
    __syncthreads();
    int warp = (blockIdx.x * blockDim.x + threadIdx.x) >> 5;
    int lane = threadIdx.x & 31;
    if (warp < M && lane < NC) {
        const float* a = A + (size_t)warp * 128;
        float acc = 0.f;
        #pragma unroll 8
        for (int k = 0; k < 128; k++) acc += a[k] * sW[k * NC + lane];
        C[warp * NC + lane] = acc;
    }
}

// ---------------- attention logits el/er ----------------
__global__ void k_elr(const float* __restrict__ feat, const float* __restrict__ al,
                      const float* __restrict__ ar, float* el, float* er) {
    int idx = blockIdx.x * blockDim.x + threadIdx.x;
    if (idx >= N_NODES * HEADS) return;
    int i = idx >> 3, h = idx & 7;
    const float* f = feat + (size_t)i * F + h * HID;
    float a = 0.f, b = 0.f;
    #pragma unroll
    for (int d = 0; d < HID; d++) {
        float v = f[d];
        a += v * al[h * HID + d];
        b += v * ar[h * HID + d];
    }
    el[idx] = a;
    er[idx] = b;
}

__global__ void k_elr10(const float* __restrict__ feat, const float* __restrict__ al,
                        const float* __restrict__ ar, float* el, float* er) {
    int i = blockIdx.x * blockDim.x + threadIdx.x;
    if (i >= N_NODES) return;
    const float* f = feat + (size_t)i * NC;
    float a = 0.f, b = 0.f;
    #pragma unroll
    for (int d = 0; d < NC; d++) { float v = f[d]; a += v * al[d]; b += v * ar[d]; }
    el[i] = a;
    er[i] = b;
}

// ---------------- edge softmax + aggregation, CSR by dst ----------------
// one block (128 threads) per dst node; thread t owns feature t, head = t>>4
__global__ __launch_bounds__(128) void k_edge(const float* __restrict__ feat,
                                              const float* __restrict__ el,
                                              const float* __restrict__ er,
                                              const int* __restrict__ rowptr,
                                              const int* __restrict__ esrc,
                                              float* __restrict__ hout, int activate) {
    int i = blockIdx.x;
    int t = threadIdx.x;
    int h = t >> 4, lane = t & 15;
    int b = rowptr[i], e = rowptr[i + 1];
    float er_h = er[i * HEADS + h];

    __shared__ float s_max[HEADS];
    __shared__ float s_den[HEADS];

    // pass A: per-head max of leaky_relu(el[src]+er[dst])
    float m = -FLT_MAX;
    for (int j = b + lane; j < e; j += 16) {
        int s = esrc[j];
        float x = el[s * HEADS + h] + er_h;
        x = x > 0.f ? x : NEG * x;
        m = fmaxf(m, x);
    }
    #pragma unroll
    for (int o = 8; o; o >>= 1) m = fmaxf(m, __shfl_xor_sync(0xffffffffu, m, o, 16));
    if (lane == 0) s_max[h] = m;
    __syncthreads();
    float emax = s_max[h];

    // pass B: softmax weights + feature aggregation in registers
    float acc = 0.f, den = 0.f;
    for (int j = b; j < e; j++) {
        int s = esrc[j];
        float x = el[s * HEADS + h] + er_h;
        x = x > 0.f ? x : NEG * x;
        float ex = __expf(x - emax);
        den += ex;
        acc += feat[(size_t)s * F + t] * ex;
    }
    if (lane == 0) s_den[h] = den;
    __syncthreads();
    float d = s_den[h];
    float o = d > 0.f ? acc / d : 0.f;
    if (activate) o = o > 0.f ? o : expm1f(o);
    hout[(size_t)i * F + t] = o;
}

// final layer: 1 head, 10 classes, one warp per node
__global__ __launch_bounds__(32) void k_edge10(const float* __restrict__ feat,
                                               const float* __restrict__ el,
                                               const float* __restrict__ er,
                                               const int* __restrict__ rowptr,
                                               const int* __restrict__ esrc,
                                               float* __restrict__ out) {
    int i = blockIdx.x;
    int lane = threadIdx.x;
    int b = rowptr[i], e = rowptr[i + 1];
    float er_i = er[i];

    float m = -FLT_MAX;
    for (int j = b + lane; j < e; j += 32) {
        float x = el[esrc[j]] + er_i;
        x = x > 0.f ? x : NEG * x;
        m = fmaxf(m, x);
    }
    #pragma unroll
    for (int o = 16; o; o >>= 1) m = fmaxf(m, __shfl_xor_sync(0xffffffffu, m, o));

    float acc = 0.f, den = 0.f;
    for (int j = b; j < e; j++) {
        int s = esrc[j];
        float x = el[s] + er_i;
        x = x > 0.f ? x : NEG * x;
        float ex = __expf(x - m);
        den += ex;
        if (lane < NC) acc += feat[(size_t)s * NC + lane] * ex;
    }
    float o = den > 0.f ? acc / den : 0.f;
    if (lane < NC) out[(size_t)i * NC + lane] = o;
}

// ---------------- launch ----------------
extern "C" void kernel_launch(void* const* d_in, const int* in_sizes, int n_in,
                              void* d_out, int out_size) {
    const float* h   = (const float*)d_in[0];
    const int*   src = (const int*)d_in[1];
    const int*   dst = (const int*)d_in[2];
    const float *W[5], *al[5], *ar[5];
    for (int i = 0; i < 5; i++) {
        W[i]  = (const float*)d_in[3 + 3 * i];
        al[i] = (const float*)d_in[4 + 3 * i];
        ar[i] = (const float*)d_in[5 + 3 * i];
    }
    float* out = (float*)d_out;

    float *feat, *hbuf, *el, *er, *feat10;
    int *cnt, *inc, *bsum, *rowptr, *cursor, *esrc;
    cudaGetSymbolAddress((void**)&feat,   g_feat);
    cudaGetSymbolAddress((void**)&hbuf,   g_h);
    cudaGetSymbolAddress((void**)&el,     g_el);
    cudaGetSymbolAddress((void**)&er,     g_er);
    cudaGetSymbolAddress((void**)&feat10, g_feat10);
    cudaGetSymbolAddress((void**)&cnt,    g_cnt);
    cudaGetSymbolAddress((void**)&inc,    g_inc);
    cudaGetSymbolAddress((void**)&bsum,   g_bsum);
    cudaGetSymbolAddress((void**)&rowptr, g_rowptr);
    cudaGetSymbolAddress((void**)&cursor, g_cursor);
    cudaGetSymbolAddress((void**)&esrc,   g_esrc);

    const int NB_SCAN = (N_NODES + 1023) / 1024;  // 49

    // CSR by dst
    k_zero<<<(N_NODES + 255) / 256, 256>>>(cnt, N_NODES);
    k_hist<<<(N_EDGES + 255) / 256, 256>>>(dst, cnt, N_EDGES);
    k_scan1<<<NB_SCAN, 1024>>>(cnt, inc, bsum, N_NODES);
    k_scan2<<<1, 32>>>(bsum, NB_SCAN);
    k_finalize<<<(N_NODES + 255) / 256, 256>>>(inc, bsum, cnt, rowptr, cursor, N_NODES);
    k_scatter<<<(N_EDGES + 255) / 256, 256>>>(src, dst, cursor, esrc, N_EDGES);

    // 4 GAT layers (128 -> 8x16, ELU)
    const float* hin = h;
    for (int l = 0; l < 4; l++) {
        k_gemm128<<<(N_NODES + 63) / 64, 256>>>(hin, W[l], feat, N_NODES);
        k_elr<<<(N_NODES * HEADS + 255) / 256, 256>>>(feat, al[l], ar[l], el, er);
        k_edge<<<N_NODES, 128>>>(feat, el, er, rowptr, esrc, hbuf, 1);
        hin = hbuf;
    }

    // final layer (128 -> 1x10, no activation; mean over 1 head = identity)
    k_gemm10<<<(N_NODES + 7) / 8, 256>>>(hbuf, W[4], feat10, N_NODES);
    k_elr10<<<(N_NODES + 255) / 256, 256>>>(feat10, al[4], ar[4], el, er);
    k_edge10<<<N_NODES, 32>>>(feat10, el, er, rowptr, esrc, out);
}